// round 15
// baseline (speedup 1.0000x reference)
#include <cuda_runtime.h>
#include <cuda_bf16.h>
#include <cuda_fp16.h>
#include <math.h>
#include <stdint.h>

#define NN 20000
#define FF 256
#define HH 8
#define DD 64
#define HD 512
#define MM 2
#define EE 320000
#define CC 5
#define HIDD 128
#define SB 40          // scan blocks per metapath (40*512 >= NN)

// mega-prep block ranges
#define MP_WTR 256     // W transpose tiles: 16 x 8 x 2
#define MP_STR 64      // sW1 transpose tiles: 4 x 16
#define MP_HCV 400     // h convert blocks
#define MP_HIST 2500   // hist blocks (2500*256 = 640000 edges)
#define MP_TOTAL (MP_WTR + MP_STR + MP_HCV + MP_HIST)

// ---------------- scratch (device globals; no allocation) ----------------
__device__ __half g_h16[NN * FF];
__device__ __half g_Wt16[MM * HD * FF];
__device__ __half g_sW1t16[HIDD * HD];
__device__ __half g_feat[MM * NN * HD];
__device__ __half g_z[MM * NN * HD];
__device__ float g_el[MM * NN * HH];
__device__ float g_er[MM * NN * HH];
__device__ int   g_hist[MM * NN];
__device__ int   g_rowptr[MM * (NN + 1)];
__device__ int   g_cursor[MM * NN];
__device__ int   g_bsum[MM * SB];
__device__ int   g_sflag[MM * SB];
__device__ int   g_src_s[MM * EE];
__device__ float g_s[MM * NN];
__device__ float g_y[MM * NN * CC];
__device__ float g_sum[MM];

__device__ __forceinline__ uint32_t f2h2(float a, float b) {
    __half2 h = __floats2half2_rn(a, b);
    return *(uint32_t*)&h;
}

// ---------------- zero hist/s/sum/flags (precedes mega_prep atomics) -------
__global__ void zero_hist_kernel() {
    int i = blockIdx.x * blockDim.x + threadIdx.x;
    int total = MM * NN;
    for (; i < total; i += gridDim.x * blockDim.x) {
        g_hist[i] = 0;
        g_s[i] = 0.0f;
    }
    if (blockIdx.x == 0 && threadIdx.x < MM * SB) g_sflag[threadIdx.x] = 0;
    if (blockIdx.x == 0 && threadIdx.x < MM) g_sum[threadIdx.x] = 0.0f;
}

// ---------------- mega-prep: W^T + sW1^T + h convert + hist, one launch -----
__global__ void mega_prep(const float* __restrict__ h, const float* __restrict__ W,
                          const float* __restrict__ sW1, const int* __restrict__ dst) {
    __shared__ float tile[32][33];
    int b = blockIdx.x;
    int t = threadIdx.x;
    if (b < MP_WTR) {
        // W transpose: Wt[m][n][k] = W[m][k][n]; K=FF rows, N=HD cols
        int m = b >> 7;
        int r = b & 127;
        int ky = r >> 4;             // 0..7   (FF/32)
        int nx = r & 15;             // 0..15  (HD/32)
        const float* src = W + (size_t)m * FF * HD;
        __half* dstp = g_Wt16 + (size_t)m * HD * FF;
        int nt = nx * 32, kt = ky * 32;
        int tx = t & 31, ty = t >> 5;
#pragma unroll
        for (int i = 0; i < 32; i += 8)
            tile[ty + i][tx] = src[(size_t)(kt + ty + i) * HD + nt + tx];
        __syncthreads();
#pragma unroll
        for (int i = 0; i < 32; i += 8)
            dstp[(size_t)(nt + ty + i) * FF + kt + tx] = __float2half(tile[tx][ty + i]);
    } else if (b < MP_WTR + MP_STR) {
        // sW1 transpose: K=HD rows, N=HIDD cols
        int r = b - MP_WTR;
        int ky = r >> 2;             // 0..15  (HD/32)
        int nx = r & 3;              // 0..3   (HIDD/32)
        int nt = nx * 32, kt = ky * 32;
        int tx = t & 31, ty = t >> 5;
#pragma unroll
        for (int i = 0; i < 32; i += 8)
            tile[ty + i][tx] = sW1[(size_t)(kt + ty + i) * HIDD + nt + tx];
        __syncthreads();
#pragma unroll
        for (int i = 0; i < 32; i += 8)
            g_sW1t16[(size_t)(nt + ty + i) * HD + kt + tx] = __float2half(tile[tx][ty + i]);
    } else if (b < MP_WTR + MP_STR + MP_HCV) {
        int lt = (b - MP_WTR - MP_STR) * 256 + t;
        int stride = MP_HCV * 256;
        for (int i = lt; i < NN * FF / 4; i += stride) {
            float4 v = ((const float4*)h)[i];
            ((uint2*)g_h16)[i] = make_uint2(f2h2(v.x, v.y), f2h2(v.z, v.w));
        }
    } else {
        int e = (b - MP_WTR - MP_STR - MP_HCV) * 256 + t;
        if (e < MM * EE) {
            int m = e / EE;
            atomicAdd(&g_hist[m * NN + dst[e]], 1);
        }
    }
}

// ---------------- fused scan: block-local + publish/wait offsets -----------
__global__ void scan_kernel() {
    int m = blockIdx.y, b = blockIdx.x, t = threadIdx.x;
    int idx = b * 512 + t;
    int v = (idx < NN) ? g_hist[m * NN + idx] : 0;
    __shared__ int sh[512];
    sh[t] = v;
    __syncthreads();
    for (int off = 1; off < 512; off <<= 1) {
        int x = (t >= off) ? sh[t - off] : 0;
        __syncthreads();
        sh[t] += x;
        __syncthreads();
    }
    int excl = sh[t] - v;   // block-local exclusive
    // publish block total
    if (t == 511) {
        g_bsum[m * SB + b] = sh[511];
        __threadfence();
        atomicExch(&g_sflag[m * SB + b], 1);
    }
    // block offset = sum of previous block totals (parallel wait)
    __shared__ int off;
    if (t == 0) {
        int s = 0;
        for (int i = 0; i < b; i++) {
            while (atomicAdd(&g_sflag[m * SB + i], 0) == 0) { }
            s += g_bsum[m * SB + i];
        }
        off = s;
    }
    __syncthreads();
    if (idx < NN) {
        int r = excl + off;
        g_rowptr[m * (NN + 1) + idx] = r;
        g_cursor[m * NN + idx] = r;
    }
    if (b == 0 && t == 0) g_rowptr[m * (NN + 1) + NN] = EE;
}

// ---------------- FP16 MMA GEMM, cp.async 2-stage pipeline, GBK=32 ---------
#define GBM 128
#define GBN 128
#define GBK 32
#define SMSH 40
#define ASTGB (GBM * SMSH * 2)
#define BSTGB (GBN * SMSH * 2)

#define LDSM4(r, addr)                                                          \
    asm volatile("ldmatrix.sync.aligned.m8n8.x4.shared.b16 {%0,%1,%2,%3}, [%4];" \
                 : "=r"((r)[0]), "=r"((r)[1]), "=r"((r)[2]), "=r"((r)[3])        \
                 : "r"(addr))

#define CP16(dst, src, sz)                                                       \
    asm volatile("cp.async.cg.shared.global [%0], [%1], 16, %2;"                 \
                 :: "r"(dst), "l"(src), "r"(sz))

__device__ __forceinline__ void mma_f16(float4& d,
                                        uint32_t a0, uint32_t a1, uint32_t a2, uint32_t a3,
                                        uint32_t b0, uint32_t b1) {
    asm volatile("mma.sync.aligned.m16n8k16.row.col.f32.f16.f16.f32 "
                 "{%0,%1,%2,%3}, {%4,%5,%6,%7}, {%8,%9}, {%0,%1,%2,%3};"
                 : "+f"(d.x), "+f"(d.y), "+f"(d.z), "+f"(d.w)
                 : "r"(a0), "r"(a1), "r"(a2), "r"(a3), "r"(b0), "r"(b1));
}

__global__ __launch_bounds__(256) void gemm_mma(
    const __half* __restrict__ A, const __half* __restrict__ Bt, __half* __restrict__ C,
    int Mrows, int K, int Ncols, const float* __restrict__ bias, int mode,
    long aStride, long bStride, long cStride,
    const float* __restrict__ attl, const float* __restrict__ attr,
    const float* __restrict__ w2) {
    int bz = blockIdx.z;
    A += (size_t)bz * aStride;
    Bt += (size_t)bz * bStride;
    C += (size_t)bz * cStride;

    __shared__ __align__(16) __half As[2][GBM * SMSH];
    __shared__ __align__(16) __half Bs[2][GBN * SMSH];

    int tid = threadIdx.x;
    int warp = tid >> 5;
    int lane = tid & 31;
    int warpM = warp >> 1;
    int warpN = warp & 1;
    int group = lane >> 2;
    int tig = lane & 3;

    int rowBase = blockIdx.y * GBM;
    int colBase = blockIdx.x * GBN;

    int cRow = tid >> 1;
    int cHalf = (tid & 1) * 16;

    int gaRow = rowBase + cRow;
    uint32_t aSz = (gaRow < Mrows) ? 16u : 0u;
    const __half* aSrcBase = A + (size_t)gaRow * K + cHalf;
    const __half* bSrcBase = Bt + (size_t)(colBase + cRow) * K + cHalf;

    uint32_t AsU = (uint32_t)__cvta_generic_to_shared(&As[0][0]);
    uint32_t BsU = (uint32_t)__cvta_generic_to_shared(&Bs[0][0]);
    uint32_t aDst = AsU + (uint32_t)((cRow * SMSH + cHalf) * 2);
    uint32_t bDst = BsU + (uint32_t)((cRow * SMSH + cHalf) * 2);

    uint32_t aPtr = AsU + (uint32_t)(((warpM * 32 + (lane & 15)) * SMSH) * 2 + (lane >> 4) * 16);
    uint32_t bPtr = BsU + (uint32_t)(((warpN * 64 + (lane >> 4) * 8 + (lane & 7)) * SMSH) * 2
                                     + (((lane >> 3) & 1) * 16));

    float4 acc[2][8];
#pragma unroll
    for (int i = 0; i < 2; i++)
#pragma unroll
        for (int j = 0; j < 8; j++) acc[i][j] = make_float4(0.f, 0.f, 0.f, 0.f);

    CP16(aDst, aSrcBase, aSz);
    CP16(aDst + 16, aSrcBase + 8, aSz);
    CP16(bDst, bSrcBase, 16u);
    CP16(bDst + 16, bSrcBase + 8, 16u);
    asm volatile("cp.async.commit_group;");

    int niter = K / GBK;
    for (int i = 0; i < niter; i++) {
        asm volatile("cp.async.wait_group 0;");
        __syncthreads();
        if (i + 1 < niter) {
            int k0 = (i + 1) * GBK;
            uint32_t so = (uint32_t)((i + 1) & 1);
            CP16(aDst + so * ASTGB, aSrcBase + k0, aSz);
            CP16(aDst + so * ASTGB + 16, aSrcBase + k0 + 8, aSz);
            CP16(bDst + so * BSTGB, bSrcBase + k0, 16u);
            CP16(bDst + so * BSTGB + 16, bSrcBase + k0 + 8, 16u);
        }
        asm volatile("cp.async.commit_group;");

        uint32_t aP = aPtr + (i & 1) * ASTGB;
        uint32_t bP = bPtr + (i & 1) * BSTGB;
#pragma unroll
        for (int kk = 0; kk < 2; kk++) {
            uint32_t kb = kk * 32;
            uint32_t af[2][4];
            LDSM4(af[0], aP + kb);
            LDSM4(af[1], aP + 16 * SMSH * 2 + kb);
            uint32_t bfr[4][4];
#pragma unroll
            for (int p = 0; p < 4; p++) LDSM4(bfr[p], bP + p * 16 * SMSH * 2 + kb);
#pragma unroll
            for (int mt = 0; mt < 2; mt++)
#pragma unroll
                for (int nt = 0; nt < 8; nt++)
                    mma_f16(acc[mt][nt], af[mt][0], af[mt][1], af[mt][2], af[mt][3],
                            bfr[nt >> 1][(nt & 1) * 2], bfr[nt >> 1][(nt & 1) * 2 + 1]);
        }
    }

    if (mode == 2) {
        int head = blockIdx.x * 2 + warpN;
        const float* alp = attl + (bz * HH + head) * DD;
        const float* arp = attr + (bz * HH + head) * DD;
        float sl[2][2] = {{0.f, 0.f}, {0.f, 0.f}};
        float sr[2][2] = {{0.f, 0.f}, {0.f, 0.f}};
#pragma unroll
        for (int mt = 0; mt < 2; mt++) {
            int row0 = rowBase + warpM * 32 + mt * 16 + group;
            int row1 = row0 + 8;
#pragma unroll
            for (int nt = 0; nt < 8; nt++) {
                int cl = nt * 8 + 2 * tig;
                float4 v = acc[mt][nt];
                float a0 = alp[cl], a1 = alp[cl + 1];
                float r0 = arp[cl], r1 = arp[cl + 1];
                sl[mt][0] += v.x * a0 + v.y * a1;
                sl[mt][1] += v.z * a0 + v.w * a1;
                sr[mt][0] += v.x * r0 + v.y * r1;
                sr[mt][1] += v.z * r0 + v.w * r1;
                int col = colBase + warpN * 64 + cl;
                if (row0 < Mrows) *(uint32_t*)(C + (size_t)row0 * Ncols + col) = f2h2(v.x, v.y);
                if (row1 < Mrows) *(uint32_t*)(C + (size_t)row1 * Ncols + col) = f2h2(v.z, v.w);
            }
        }
#pragma unroll
        for (int mt = 0; mt < 2; mt++)
#pragma unroll
            for (int r = 0; r < 2; r++) {
                sl[mt][r] += __shfl_xor_sync(0xffffffffu, sl[mt][r], 1);
                sl[mt][r] += __shfl_xor_sync(0xffffffffu, sl[mt][r], 2);
                sr[mt][r] += __shfl_xor_sync(0xffffffffu, sr[mt][r], 1);
                sr[mt][r] += __shfl_xor_sync(0xffffffffu, sr[mt][r], 2);
            }
        if (tig == 0) {
#pragma unroll
            for (int mt = 0; mt < 2; mt++) {
                int row0 = rowBase + warpM * 32 + mt * 16 + group;
                int row1 = row0 + 8;
                if (row0 < Mrows) {
                    g_el[(bz * NN + row0) * HH + head] = sl[mt][0];
                    g_er[(bz * NN + row0) * HH + head] = sr[mt][0];
                }
                if (row1 < Mrows) {
                    g_el[(bz * NN + row1) * HH + head] = sl[mt][1];
                    g_er[(bz * NN + row1) * HH + head] = sr[mt][1];
                }
            }
        }
    } else {
        float sp[2][2] = {{0.f, 0.f}, {0.f, 0.f}};
#pragma unroll
        for (int mt = 0; mt < 2; mt++) {
#pragma unroll
            for (int nt = 0; nt < 8; nt++) {
                int col = colBase + warpN * 64 + nt * 8 + 2 * tig;
                float b0 = bias[col], b1 = bias[col + 1];
                float w0 = w2[col], w1 = w2[col + 1];
                float4 v = acc[mt][nt];
                sp[mt][0] += tanhf(v.x + b0) * w0 + tanhf(v.y + b1) * w1;
                sp[mt][1] += tanhf(v.z + b0) * w0 + tanhf(v.w + b1) * w1;
            }
        }
#pragma unroll
        for (int mt = 0; mt < 2; mt++)
#pragma unroll
            for (int r = 0; r < 2; r++) {
                sp[mt][r] += __shfl_xor_sync(0xffffffffu, sp[mt][r], 1);
                sp[mt][r] += __shfl_xor_sync(0xffffffffu, sp[mt][r], 2);
            }
        if (tig == 0) {
#pragma unroll
            for (int mt = 0; mt < 2; mt++) {
                int row0 = rowBase + warpM * 32 + mt * 16 + group;
                int row1 = row0 + 8;
                if (row0 < Mrows) atomicAdd(&g_s[row0], sp[mt][0]);
                if (row1 < Mrows) atomicAdd(&g_s[row1], sp[mt][1]);
            }
        }
    }
}

// ---------------- scatter: CSR src ordering only (no exp, no el/er) ---------
__global__ void scatter_kernel(const int* __restrict__ src, const int* __restrict__ dst) {
    int tid = blockIdx.x * blockDim.x + threadIdx.x;
    int e = tid * 4;
    if (e >= MM * EE) return;
    int4 sv = *(const int4*)(src + e);
    int4 dv = *(const int4*)(dst + e);
    int m0 = e / EE, m1 = (e + 1) / EE, m2 = (e + 2) / EE, m3 = (e + 3) / EE;
    int p0 = atomicAdd(&g_cursor[m0 * NN + dv.x], 1);
    int p1 = atomicAdd(&g_cursor[m1 * NN + dv.y], 1);
    int p2 = atomicAdd(&g_cursor[m2 * NN + dv.z], 1);
    int p3 = atomicAdd(&g_cursor[m3 * NN + dv.w], 1);
    g_src_s[m0 * EE + p0] = sv.x;
    g_src_s[m1 * EE + p1] = sv.y;
    g_src_s[m2 * EE + p2] = sv.z;
    g_src_s[m3 * EE + p3] = sv.w;
}

// ---------------- aggregation: inline exp + fused classifier ----------------
__global__ void agg_kernel(const float* __restrict__ bg, const float* __restrict__ pW) {
    int n = blockIdx.x;
    int m = blockIdx.y;
    int t = threadIdx.x;           // 0..127, owns dims [4t, 4t+4)
    int h = t >> 4;
    int beg = g_rowptr[m * (NN + 1) + n];
    int end = g_rowptr[m * (NN + 1) + n + 1];
    float ax = 0.f, ay = 0.f, az = 0.f, aw = 0.f;
    float dsum = 0.f;
    const __half* featB = g_feat + (size_t)m * NN * HD + t * 4;
    const float* elB = g_el + (size_t)m * NN * HH + h;
    float erh = g_er[((size_t)m * NN + n) * HH + h];
    int j = beg;
    for (; j + 3 < end; j += 4) {
        int gp = m * EE + j;
        int s0 = __ldg(&g_src_s[gp]);
        int s1 = __ldg(&g_src_s[gp + 1]);
        int s2 = __ldg(&g_src_s[gp + 2]);
        int s3 = __ldg(&g_src_s[gp + 3]);
        float l0 = __ldg(elB + (size_t)s0 * HH);
        float l1 = __ldg(elB + (size_t)s1 * HH);
        float l2 = __ldg(elB + (size_t)s2 * HH);
        float l3 = __ldg(elB + (size_t)s3 * HH);
        uint2 v0 = __ldg((const uint2*)(featB + (size_t)s0 * HD));
        uint2 v1 = __ldg((const uint2*)(featB + (size_t)s1 * HD));
        uint2 v2 = __ldg((const uint2*)(featB + (size_t)s2 * HD));
        uint2 v3 = __ldg((const uint2*)(featB + (size_t)s3 * HD));
        float w;
        w = l0 + erh; w = w > 0.f ? w : 0.2f * w; float e0 = expf(w);
        w = l1 + erh; w = w > 0.f ? w : 0.2f * w; float e1 = expf(w);
        w = l2 + erh; w = w > 0.f ? w : 0.2f * w; float e2 = expf(w);
        w = l3 + erh; w = w > 0.f ? w : 0.2f * w; float e3 = expf(w);
        dsum += (e0 + e1) + (e2 + e3);
        float2 a01, a23;
        a01 = __half22float2(*(__half2*)&v0.x); a23 = __half22float2(*(__half2*)&v0.y);
        ax += e0 * a01.x; ay += e0 * a01.y; az += e0 * a23.x; aw += e0 * a23.y;
        a01 = __half22float2(*(__half2*)&v1.x); a23 = __half22float2(*(__half2*)&v1.y);
        ax += e1 * a01.x; ay += e1 * a01.y; az += e1 * a23.x; aw += e1 * a23.y;
        a01 = __half22float2(*(__half2*)&v2.x); a23 = __half22float2(*(__half2*)&v2.y);
        ax += e2 * a01.x; ay += e2 * a01.y; az += e2 * a23.x; aw += e2 * a23.y;
        a01 = __half22float2(*(__half2*)&v3.x); a23 = __half22float2(*(__half2*)&v3.y);
        ax += e3 * a01.x; ay += e3 * a01.y; az += e3 * a23.x; aw += e3 * a23.y;
    }
    for (; j < end; j++) {
        int gp = m * EE + j;
        int s = __ldg(&g_src_s[gp]);
        float l = __ldg(elB + (size_t)s * HH);
        float w = l + erh; w = w > 0.f ? w : 0.2f * w;
        float exv = expf(w);
        dsum += exv;
        uint2 fv = __ldg((const uint2*)(featB + (size_t)s * HD));
        float2 f01 = __half22float2(*(__half2*)&fv.x);
        float2 f23 = __half22float2(*(__half2*)&fv.y);
        ax += exv * f01.x; ay += exv * f01.y; az += exv * f23.x; aw += exv * f23.y;
    }
    float inv = 1.0f / fmaxf(dsum, 1e-9f);
    const float* bp = bg + m * HD + t * 4;
    float o0 = ax * inv + bp[0], o1 = ay * inv + bp[1];
    float o2 = az * inv + bp[2], o3 = aw * inv + bp[3];
    o0 = o0 > 0.f ? o0 : expf(o0) - 1.0f;
    o1 = o1 > 0.f ? o1 : expf(o1) - 1.0f;
    o2 = o2 > 0.f ? o2 : expf(o2) - 1.0f;
    o3 = o3 > 0.f ? o3 : expf(o3) - 1.0f;
    *(uint2*)(g_z + ((size_t)(m * NN + n)) * HD + t * 4) =
        make_uint2(f2h2(o0, o1), f2h2(o2, o3));

    const float* w = pW + (size_t)t * 4 * CC;
    float yc[CC];
#pragma unroll
    for (int c = 0; c < CC; c++)
        yc[c] = o0 * w[c] + o1 * w[CC + c] + o2 * w[2 * CC + c] + o3 * w[3 * CC + c];
#pragma unroll
    for (int c = 0; c < CC; c++)
#pragma unroll
        for (int off = 16; off > 0; off >>= 1)
            yc[c] += __shfl_down_sync(0xffffffffu, yc[c], off);
    __shared__ float ysh[4][CC];
    int warp = t >> 5, lane = t & 31;
    if (lane == 0)
#pragma unroll
        for (int c = 0; c < CC; c++) ysh[warp][c] = yc[c];
    __syncthreads();
    if (t < CC) {
        float v = ysh[0][t] + ysh[1][t] + ysh[2][t] + ysh[3][t];
        g_y[((size_t)m * NN + n) * CC + t] = v;
    }
}

// ---------------- mean over nodes per metapath ----------------
__global__ void reduce_kernel() {
    int m = blockIdx.y;
    int t = threadIdx.x;
    float s = 0.f;
    for (int i = blockIdx.x * blockDim.x + t; i < NN; i += gridDim.x * blockDim.x)
        s += g_s[m * NN + i];
    __shared__ float sh[256];
    sh[t] = s;
    __syncthreads();
    for (int off = 128; off > 0; off >>= 1) {
        if (t < off) sh[t] += sh[t + off];
        __syncthreads();
    }
    if (t == 0) atomicAdd(&g_sum[m], sh[0]);
}

// ---------------- final: beta inline + out = b0*y0 + b1*y1 + pb -------------
__global__ void final_kernel(const float* __restrict__ pb, float* __restrict__ out) {
    int tid = blockIdx.x * blockDim.x + threadIdx.x;
    if (tid >= NN * CC) return;
    float a = g_sum[0] * (1.0f / NN);
    float b = g_sum[1] * (1.0f / NN);
    float mx = fmaxf(a, b);
    float e0 = expf(a - mx), e1 = expf(b - mx);
    float inv = 1.0f / (e0 + e1);
    float b0 = e0 * inv, b1 = e1 * inv;
    int c = tid % CC;
    out[tid] = b0 * g_y[tid] + b1 * g_y[NN * CC + tid] + pb[c];
}

// ---------------- launch ----------------
extern "C" void kernel_launch(void* const* d_in, const int* in_sizes, int n_in,
                              void* d_out, int out_size) {
    const float* h    = (const float*)d_in[0];
    const int*   src  = (const int*)d_in[1];
    const int*   dst  = (const int*)d_in[2];
    const float* W    = (const float*)d_in[3];
    const float* al   = (const float*)d_in[4];
    const float* ar   = (const float*)d_in[5];
    const float* bg   = (const float*)d_in[6];
    const float* sW1  = (const float*)d_in[7];
    const float* sb1  = (const float*)d_in[8];
    const float* sW2  = (const float*)d_in[9];
    const float* pW   = (const float*)d_in[10];
    const float* pb   = (const float*)d_in[11];
    float* out = (float*)d_out;

    __half *p_h16, *p_Wt16, *p_sW1t16, *p_feat, *p_z;
    cudaGetSymbolAddress((void**)&p_h16, g_h16);
    cudaGetSymbolAddress((void**)&p_Wt16, g_Wt16);
    cudaGetSymbolAddress((void**)&p_sW1t16, g_sW1t16);
    cudaGetSymbolAddress((void**)&p_feat, g_feat);
    cudaGetSymbolAddress((void**)&p_z, g_z);

    zero_hist_kernel<<<80, 512>>>();                               // 1
    mega_prep<<<MP_TOTAL, 256>>>(h, W, sW1, dst);                  // 2
    scan_kernel<<<dim3(SB, MM), 512>>>();                          // 3
    scatter_kernel<<<(MM * EE / 4 + 255) / 256, 256>>>(src, dst);  // 4

    // 5: feat[m] = h @ W[m], fused el/er epilogue (2 heads per CTA)
    gemm_mma<<<dim3(HD / GBN, (NN + GBM - 1) / GBM, MM), 256>>>(
        p_h16, p_Wt16, p_feat, NN, FF, HD, nullptr, 2,
        0L, (long)HD * FF, (long)NN * HD, al, ar, nullptr);

    agg_kernel<<<dim3(NN, MM), 128>>>(bg, pW);                     // 6

    // 7: semantic — s[row] += sum tanh(z@W1 + b1) * W2, no C write
    gemm_mma<<<dim3(HIDD / GBN, (MM * NN + GBM - 1) / GBM, 1), 256>>>(
        p_z, p_sW1t16, nullptr, MM * NN, HD, HIDD, sb1, 3,
        0L, 0L, 0L, nullptr, nullptr, sW2);

    reduce_kernel<<<dim3(40, MM), 256>>>();                        // 8
    final_kernel<<<(NN * CC + 255) / 256, 256>>>(pb, out);         // 9
}